// round 5
// baseline (speedup 1.0000x reference)
#include <cuda_runtime.h>
#include <cuda_bf16.h>
#include <cstdint>
#include <math.h>

using bf16 = __nv_bfloat16;

// Shapes
// B=8, S=2048, D_IN=D_HID=D_OUT=1024
#define NROWS (16384)        // B*S
#define DD    (1024)
#define SS    (2048)
#define NB    (8)

// ---------------------------------------------------------------------------
// Device scratch (allocation-free rule: __device__ globals)
// ---------------------------------------------------------------------------
__device__ __align__(16) bf16  g_xb [16384LL*1024];
__device__ __align__(16) bf16  g_wq [1024LL*1024];
__device__ __align__(16) bf16  g_wk [1024LL*1024];
__device__ __align__(16) bf16  g_wv [1024LL*1024];
__device__ __align__(16) bf16  g_wo [1024LL*1024];
__device__ __align__(16) bf16  g_q  [16384LL*1024];
__device__ __align__(16) bf16  g_k  [16384LL*1024];
__device__ __align__(16) bf16  g_v  [16384LL*1024];
__device__ __align__(16) bf16  g_vt [8LL*1024*2048];   // [b][h][s]
__device__ __align__(16) bf16  g_s  [8LL*2048*2048];   // scores / attn
__device__ __align__(16) bf16  g_w  [16384LL*1024];    // weighted
__device__ __align__(16) float g_pre[16384LL*1024];    // pre-LayerNorm

// ---------------------------------------------------------------------------
// fp32 -> bf16 convert
// ---------------------------------------------------------------------------
__global__ void cvt_k(const float* __restrict__ in, bf16* __restrict__ out, int n) {
    for (int i = blockIdx.x * blockDim.x + threadIdx.x; i < n;
         i += gridDim.x * blockDim.x)
        out[i] = __float2bfloat16(in[i]);
}

// ---------------------------------------------------------------------------
// Per-batch transpose: out[b][h][s] = in[b][s][h]   (s=2048, h=1024)
// ---------------------------------------------------------------------------
__global__ void transpose_k(const bf16* __restrict__ in, bf16* __restrict__ out) {
    __shared__ bf16 t[32][33];
    const long long b = blockIdx.z;
    const bf16* ip = in  + b * 2048LL * 1024;
    bf16*       op = out + b * 2048LL * 1024;
    const int h0 = blockIdx.x * 32;
    const int s0 = blockIdx.y * 32;
    for (int i = threadIdx.y; i < 32; i += 8)
        t[i][threadIdx.x] = ip[(long long)(s0 + i) * 1024 + h0 + threadIdx.x];
    __syncthreads();
    for (int i = threadIdx.y; i < 32; i += 8)
        op[(long long)(h0 + i) * 2048 + s0 + threadIdx.x] = t[threadIdx.x][i];
}

// ---------------------------------------------------------------------------
// Row softmax over 2048 bf16 elements, in place. One block (256 thr) per row.
// ---------------------------------------------------------------------------
__global__ void softmax_k(bf16* __restrict__ S) {
    const long long row = blockIdx.x;
    bf16* p = S + row * 2048;
    const int tid = threadIdx.x;

    uint4 u = reinterpret_cast<uint4*>(p)[tid];
    __nv_bfloat162* hp = reinterpret_cast<__nv_bfloat162*>(&u);
    float v[8];
#pragma unroll
    for (int i = 0; i < 4; ++i) {
        float2 f = __bfloat1622float2(hp[i]);
        v[2 * i] = f.x; v[2 * i + 1] = f.y;
    }
    float m = v[0];
#pragma unroll
    for (int i = 1; i < 8; ++i) m = fmaxf(m, v[i]);
#pragma unroll
    for (int o = 16; o > 0; o >>= 1) m = fmaxf(m, __shfl_xor_sync(0xffffffffu, m, o));
    __shared__ float red[8];
    if ((tid & 31) == 0) red[tid >> 5] = m;
    __syncthreads();
    float mm = red[0];
#pragma unroll
    for (int j = 1; j < 8; ++j) mm = fmaxf(mm, red[j]);

    float s = 0.f;
#pragma unroll
    for (int i = 0; i < 8; ++i) { v[i] = __expf(v[i] - mm); s += v[i]; }
#pragma unroll
    for (int o = 16; o > 0; o >>= 1) s += __shfl_xor_sync(0xffffffffu, s, o);
    __syncthreads();                       // everyone done reading red (max)
    if ((tid & 31) == 0) red[tid >> 5] = s;
    __syncthreads();
    float ss = 0.f;
#pragma unroll
    for (int j = 0; j < 8; ++j) ss += red[j];
    const float inv = 1.0f / ss;

#pragma unroll
    for (int i = 0; i < 4; ++i)
        hp[i] = __floats2bfloat162_rn(v[2 * i] * inv, v[2 * i + 1] * inv);
    reinterpret_cast<uint4*>(p)[tid] = u;
}

// ---------------------------------------------------------------------------
// Row LayerNorm over 1024 fp32 elements. One block (256 thr) per row.
// ---------------------------------------------------------------------------
__global__ void ln_k(const float* __restrict__ in, const float* __restrict__ gamma,
                     const float* __restrict__ beta, float* __restrict__ out) {
    const long long row = blockIdx.x;
    const int tid = threadIdx.x;
    const float4 v = reinterpret_cast<const float4*>(in + row * 1024)[tid];
    float s = v.x + v.y + v.z + v.w;
    float q = v.x * v.x + v.y * v.y + v.z * v.z + v.w * v.w;
#pragma unroll
    for (int o = 16; o > 0; o >>= 1) {
        s += __shfl_xor_sync(0xffffffffu, s, o);
        q += __shfl_xor_sync(0xffffffffu, q, o);
    }
    __shared__ float redS[8], redQ[8];
    if ((tid & 31) == 0) { redS[tid >> 5] = s; redQ[tid >> 5] = q; }
    __syncthreads();
    float S = 0.f, Q = 0.f;
#pragma unroll
    for (int j = 0; j < 8; ++j) { S += redS[j]; Q += redQ[j]; }
    const float mu  = S * (1.0f / 1024.0f);
    const float var = Q * (1.0f / 1024.0f) - mu * mu;
    const float rs  = rsqrtf(var + 1e-5f);
    const float4 g4 = reinterpret_cast<const float4*>(gamma)[tid];
    const float4 b4 = reinterpret_cast<const float4*>(beta)[tid];
    float4 o;
    o.x = (v.x - mu) * rs * g4.x + b4.x;
    o.y = (v.y - mu) * rs * g4.y + b4.y;
    o.z = (v.z - mu) * rs * g4.z + b4.z;
    o.w = (v.w - mu) * rs * g4.w + b4.w;
    reinterpret_cast<float4*>(out + row * 1024)[tid] = o;
}

// ---------------------------------------------------------------------------
// Generic batched NT GEMM on tensor cores (bf16 in, fp32 accum):
//   C[z][m][n] (+epi) = sum_k A[z][m][k] * B[z][n][k]
// Block tile 128x128x32, 8 warps (2x4), warp tile 64x32 of m16n8k16 mmas,
// 2-stage cp.async pipeline, padded smem (row stride 40 bf16, conflict-free
// for ldmatrix: 8 rows x 20-word stride hit distinct banks).
// MODE 0: +bias, store bf16     (QKV projections)
// MODE 1: *scale, store bf16    (QK^T scores)
// MODE 2: plain, store bf16     (attn @ V)
// MODE 3: +bias +fp32 residual, store fp32 (output projection, pre-LN)
// ---------------------------------------------------------------------------
#define SAPAD 40
#define BUFB  (128 * SAPAD * 2)   // bytes per smem buffer

__device__ __forceinline__ void issue_tile(const bf16* __restrict__ Ab, int lda,
                                           const bf16* __restrict__ Bb, int ldb,
                                           uint32_t aS, uint32_t bS, int tid, int k0) {
#pragma unroll
    for (int c = tid; c < 512; c += 256) {
        const int row = c >> 2, cc = c & 3;
        const uint32_t d = aS + (uint32_t)((row * SAPAD + cc * 8) * 2);
        const bf16* src = Ab + (long long)row * lda + (k0 + cc * 8);
        asm volatile("cp.async.cg.shared.global [%0], [%1], 16;\n" :: "r"(d), "l"(src));
    }
#pragma unroll
    for (int c = tid; c < 512; c += 256) {
        const int row = c >> 2, cc = c & 3;
        const uint32_t d = bS + (uint32_t)((row * SAPAD + cc * 8) * 2);
        const bf16* src = Bb + (long long)row * ldb + (k0 + cc * 8);
        asm volatile("cp.async.cg.shared.global [%0], [%1], 16;\n" :: "r"(d), "l"(src));
    }
    asm volatile("cp.async.commit_group;\n");
}

template <int MODE>
__global__ __launch_bounds__(256) void gemm_nt(
    const bf16* __restrict__ A, int lda, long long sAz,
    const bf16* __restrict__ Bm, int ldb, long long sBz,
    void* __restrict__ Cv, int ldc, long long sCz,
    int K,
    const float* __restrict__ bias,
    const float* __restrict__ resid, int ldr,
    float scale) {
    __shared__ bf16 sA[2][128 * SAPAD];
    __shared__ bf16 sB[2][128 * SAPAD];

    const int tid  = threadIdx.x;
    const int lane = tid & 31;
    const int warp = tid >> 5;
    const int wm   = warp >> 2;   // 0..1  (64 rows each)
    const int wn   = warp & 3;    // 0..3  (32 cols each)
    const long long z = blockIdx.z;

    const bf16* Ab = A  + z * sAz + (long long)blockIdx.y * 128 * lda;
    const bf16* Bb = Bm + z * sBz + (long long)blockIdx.x * 128 * ldb;

    const uint32_t aS0 = (uint32_t)__cvta_generic_to_shared(&sA[0][0]);
    const uint32_t bS0 = (uint32_t)__cvta_generic_to_shared(&sB[0][0]);

    float acc[4][4][4];
#pragma unroll
    for (int a = 0; a < 4; ++a)
#pragma unroll
        for (int b = 0; b < 4; ++b)
#pragma unroll
            for (int c = 0; c < 4; ++c) acc[a][b][c] = 0.f;

    const int ntk = K >> 5;
    issue_tile(Ab, lda, Bb, ldb, aS0, bS0, tid, 0);

    int buf = 0;
    for (int t = 0; t < ntk; ++t) {
        if (t + 1 < ntk) {
            issue_tile(Ab, lda, Bb, ldb,
                       aS0 + (buf ^ 1) * BUFB, bS0 + (buf ^ 1) * BUFB,
                       tid, (t + 1) << 5);
            asm volatile("cp.async.wait_group 1;\n" ::: "memory");
        } else {
            asm volatile("cp.async.wait_group 0;\n" ::: "memory");
        }
        __syncthreads();

        const uint32_t aB = aS0 + buf * BUFB;
        const uint32_t bB = bS0 + buf * BUFB;
#pragma unroll
        for (int ks = 0; ks < 2; ++ks) {
            const int kb = ks * 16;
            uint32_t af[4][4];
#pragma unroll
            for (int mt = 0; mt < 4; ++mt) {
                const int row = wm * 64 + mt * 16 + (lane & 7) + ((lane >> 3) & 1) * 8;
                const int col = kb + ((lane >> 4) << 3);
                const uint32_t ad = aB + (uint32_t)((row * SAPAD + col) * 2);
                asm volatile(
                    "ldmatrix.sync.aligned.m8n8.x4.shared.b16 {%0,%1,%2,%3}, [%4];"
                    : "=r"(af[mt][0]), "=r"(af[mt][1]), "=r"(af[mt][2]), "=r"(af[mt][3])
                    : "r"(ad));
            }
            uint32_t bfr[4][2];
#pragma unroll
            for (int nt = 0; nt < 4; ++nt) {
                const int row = wn * 32 + nt * 8 + (lane & 7);
                const int col = kb + (((lane >> 3) & 1) << 3);
                const uint32_t bd = bB + (uint32_t)((row * SAPAD + col) * 2);
                asm volatile(
                    "ldmatrix.sync.aligned.m8n8.x2.shared.b16 {%0,%1}, [%2];"
                    : "=r"(bfr[nt][0]), "=r"(bfr[nt][1])
                    : "r"(bd));
            }
#pragma unroll
            for (int mt = 0; mt < 4; ++mt)
#pragma unroll
                for (int nt = 0; nt < 4; ++nt)
                    asm volatile(
                        "mma.sync.aligned.m16n8k16.row.col.f32.bf16.bf16.f32 "
                        "{%0,%1,%2,%3}, {%4,%5,%6,%7}, {%8,%9}, {%0,%1,%2,%3};"
                        : "+f"(acc[mt][nt][0]), "+f"(acc[mt][nt][1]),
                          "+f"(acc[mt][nt][2]), "+f"(acc[mt][nt][3])
                        : "r"(af[mt][0]), "r"(af[mt][1]), "r"(af[mt][2]), "r"(af[mt][3]),
                          "r"(bfr[nt][0]), "r"(bfr[nt][1]));
        }
        __syncthreads();
        buf ^= 1;
    }

    // Epilogue. Accumulator mapping: acc[.][.][0]=(r0,c0) [1]=(r0,c0+1)
    //                                 [2]=(r0+8,c0) [3]=(r0+8,c0+1)
    const int g  = lane >> 2;
    const int tq = lane & 3;
    const int rbase = blockIdx.y * 128 + wm * 64;
    const int cbase = blockIdx.x * 128 + wn * 32;
#pragma unroll
    for (int mt = 0; mt < 4; ++mt) {
#pragma unroll
        for (int nt = 0; nt < 4; ++nt) {
            const int r0 = rbase + mt * 16 + g;
            const int c0 = cbase + nt * 8 + 2 * tq;
            float v00 = acc[mt][nt][0], v01 = acc[mt][nt][1];
            float v10 = acc[mt][nt][2], v11 = acc[mt][nt][3];
            if (MODE == 1) { v00 *= scale; v01 *= scale; v10 *= scale; v11 *= scale; }
            if (MODE == 0 || MODE == 3) {
                const float b0 = bias[c0], b1 = bias[c0 + 1];
                v00 += b0; v01 += b1; v10 += b0; v11 += b1;
            }
            if (MODE == 3) {
                float* Cf = (float*)Cv + z * sCz;
                const long long i0 = (long long)r0 * ldc + c0;
                const long long i1 = (long long)(r0 + 8) * ldc + c0;
                const float r00 = resid[(long long)r0 * ldr + c0];
                const float r01 = resid[(long long)r0 * ldr + c0 + 1];
                const float r10 = resid[(long long)(r0 + 8) * ldr + c0];
                const float r11 = resid[(long long)(r0 + 8) * ldr + c0 + 1];
                reinterpret_cast<float2*>(Cf + i0)[0] = make_float2(v00 + r00, v01 + r01);
                reinterpret_cast<float2*>(Cf + i1)[0] = make_float2(v10 + r10, v11 + r11);
            } else {
                bf16* Cb = (bf16*)Cv + z * sCz;
                reinterpret_cast<__nv_bfloat162*>(Cb + (long long)r0 * ldc + c0)[0] =
                    __floats2bfloat162_rn(v00, v01);
                reinterpret_cast<__nv_bfloat162*>(Cb + (long long)(r0 + 8) * ldc + c0)[0] =
                    __floats2bfloat162_rn(v10, v11);
            }
        }
    }
}

// ---------------------------------------------------------------------------
// Host orchestration
// ---------------------------------------------------------------------------
extern "C" void kernel_launch(void* const* d_in, const int* in_sizes, int n_in,
                              void* d_out, int out_size) {
    (void)in_sizes; (void)n_in; (void)out_size;
    const float* x     = (const float*)d_in[0];
    const float* Wq    = (const float*)d_in[1];
    const float* bq    = (const float*)d_in[2];
    const float* Wk    = (const float*)d_in[3];
    const float* bk    = (const float*)d_in[4];
    const float* Wv    = (const float*)d_in[5];
    const float* bv    = (const float*)d_in[6];
    const float* Wo    = (const float*)d_in[7];
    const float* bo    = (const float*)d_in[8];
    const float* gamma = (const float*)d_in[9];
    const float* beta  = (const float*)d_in[10];

    void *p;
    bf16 *xb, *wq, *wk, *wv, *wo, *qb, *kb, *vb, *vtb, *sb, *wtb;
    float* pre;
    cudaGetSymbolAddress(&p, g_xb);  xb  = (bf16*)p;
    cudaGetSymbolAddress(&p, g_wq);  wq  = (bf16*)p;
    cudaGetSymbolAddress(&p, g_wk);  wk  = (bf16*)p;
    cudaGetSymbolAddress(&p, g_wv);  wv  = (bf16*)p;
    cudaGetSymbolAddress(&p, g_wo);  wo  = (bf16*)p;
    cudaGetSymbolAddress(&p, g_q);   qb  = (bf16*)p;
    cudaGetSymbolAddress(&p, g_k);   kb  = (bf16*)p;
    cudaGetSymbolAddress(&p, g_v);   vb  = (bf16*)p;
    cudaGetSymbolAddress(&p, g_vt);  vtb = (bf16*)p;
    cudaGetSymbolAddress(&p, g_s);   sb  = (bf16*)p;
    cudaGetSymbolAddress(&p, g_w);   wtb = (bf16*)p;
    cudaGetSymbolAddress(&p, g_pre); pre = (float*)p;

    // 1) fp32 -> bf16 conversions
    cvt_k<<<4096, 256>>>(x,  xb, 16384 * 1024);
    cvt_k<<<2048, 256>>>(Wq, wq, 1024 * 1024);
    cvt_k<<<2048, 256>>>(Wk, wk, 1024 * 1024);
    cvt_k<<<2048, 256>>>(Wv, wv, 1024 * 1024);
    cvt_k<<<2048, 256>>>(Wo, wo, 1024 * 1024);

    const dim3 blk(256);

    // 2) QKV projections: [16384,1024] = x @ W^T + b
    const dim3 gQKV(1024 / 128, 16384 / 128, 1);
    gemm_nt<0><<<gQKV, blk>>>(xb, 1024, 0, wq, 1024, 0, qb, 1024, 0, 1024, bq, nullptr, 0, 0.f);
    gemm_nt<0><<<gQKV, blk>>>(xb, 1024, 0, wk, 1024, 0, kb, 1024, 0, 1024, bk, nullptr, 0, 0.f);
    gemm_nt<0><<<gQKV, blk>>>(xb, 1024, 0, wv, 1024, 0, vb, 1024, 0, 1024, bv, nullptr, 0, 0.f);

    // 3) V -> V^T per batch  (so attn@V is also an NT GEMM)
    transpose_k<<<dim3(1024 / 32, 2048 / 32, 8), dim3(32, 8)>>>(vb, vtb);

    // 4) scores[b] = (Q[b] @ K[b]^T) * 1/sqrt(1024)
    const dim3 gS(2048 / 128, 2048 / 128, 8);
    gemm_nt<1><<<gS, blk>>>(qb, 1024, 2048LL * 1024, kb, 1024, 2048LL * 1024,
                            sb, 2048, 2048LL * 2048, 1024, nullptr, nullptr, 0, 0.03125f);

    // 5) softmax rows (in place, fp32 math)
    softmax_k<<<16384, 256>>>(sb);

    // 6) weighted[b] = attn[b] @ V[b]   (NT against V^T)
    const dim3 gW(1024 / 128, 2048 / 128, 8);
    gemm_nt<2><<<gW, blk>>>(sb, 2048, 2048LL * 2048, vtb, 2048, 1024LL * 2048,
                            wtb, 1024, 2048LL * 1024, 2048, nullptr, nullptr, 0, 0.f);

    // 7) pre = weighted @ Wo^T + bo + x   (fp32 residual, fp32 out)
    gemm_nt<3><<<gQKV, blk>>>(wtb, 1024, 0, wo, 1024, 0, pre, 1024, 0, 1024, bo, x, 1024, 0.f);

    // 8) LayerNorm -> d_out
    ln_k<<<16384, 256>>>(pre, gamma, beta, (float*)d_out);
}